// round 1
// baseline (speedup 1.0000x reference)
#include <cuda_runtime.h>

#define Bq 8
#define Tq 2048
#define Eq 256
#define Hq 8
#define Dq 32
#define Fq 1024
#define BT (Bq*Tq)      /* 16384 */
#define BHq (Bq*Hq)     /* 64    */
#define SCALE 0.0625f   /* E^-0.5 */

// ---------------- scratch (static device globals; no allocation) ----------------
__device__ float g_xn[BT*Eq];                 // 16 MB
__device__ float g_qkv[BT*768];               // 48 MB  (cols: 0..255 q, 256..511 k, 512..767 v; col=h*32+d)
__device__ float g_attn[(size_t)BHq*Tq*Tq];   // 1 GB   scores -> attn (unnormalized e)
__device__ float g_linv[BHq*Tq];              // per-column 1/sum
__device__ float g_xh[BT*Eq];
__device__ float g_xl[BT*Eq];
__device__ float g_x2[BT*Eq];
__device__ float g_h1[(size_t)BT*Fq];         // 64 MB
__device__ float g_wpack[Eq*768];

// ---------------- fast exp on FMA pipe (avoid MUFU bottleneck) ----------------
__device__ __forceinline__ float fexp(float x){
  float t = x * 1.4426950408889634f;          // log2(e)
  t = fmaxf(t, -126.0f);
  int ei = __float2int_rd(t);
  float f = t - (float)ei;
  // 2^f, f in [0,1): degree-6 Taylor of e^(f ln2), rel err ~1e-5
  float p =            1.5403530e-4f;
  p = fmaf(p, f, 1.3333558e-3f);
  p = fmaf(p, f, 9.6181291e-3f);
  p = fmaf(p, f, 5.5504109e-2f);
  p = fmaf(p, f, 2.4022651e-1f);
  p = fmaf(p, f, 6.9314718e-1f);
  p = fmaf(p, f, 1.0f);
  return __int_as_float((ei + 127) << 23) * p;
}

// ---------------- weight packing: (H,E,D)x3 -> (E, 768) ----------------
__global__ void k_pack(const float* __restrict__ wq, const float* __restrict__ wk,
                       const float* __restrict__ wv){
  int idx = blockIdx.x*256 + threadIdx.x;     // over E*E = 65536
  if (idx >= Eq*Eq) return;
  int e = idx >> 8, c = idx & 255;
  int h = c >> 5, d = c & 31;
  int src = h*Eq*Dq + e*Dq + d;
  g_wpack[e*768 +       c] = wq[src];
  g_wpack[e*768 + 256 + c] = wk[src];
  g_wpack[e*768 + 512 + c] = wv[src];
}

// ---------------- LayerNorm: one block per row, 256 threads ----------------
__global__ void k_ln(const float* __restrict__ in, const float* __restrict__ g,
                     const float* __restrict__ b, float* __restrict__ out){
  int row = blockIdx.x, tid = threadIdx.x;
  float x = in[(size_t)row*Eq + tid];
  float s = x, s2 = x*x;
  #pragma unroll
  for (int o = 16; o > 0; o >>= 1){
    s  += __shfl_xor_sync(0xffffffffu, s,  o);
    s2 += __shfl_xor_sync(0xffffffffu, s2, o);
  }
  __shared__ float ws[8], ws2[8];
  __shared__ float smean, sinv;
  if ((tid & 31) == 0){ ws[tid>>5] = s; ws2[tid>>5] = s2; }
  __syncthreads();
  if (tid == 0){
    float t = 0.f, t2 = 0.f;
    #pragma unroll
    for (int i = 0; i < 8; i++){ t += ws[i]; t2 += ws2[i]; }
    float mean = t * (1.0f/Eq);
    float var  = t2 * (1.0f/Eq) - mean*mean;
    smean = mean;
    sinv  = rsqrtf(var + 1e-5f);
  }
  __syncthreads();
  out[(size_t)row*Eq + tid] = (x - smean)*sinv*g[tid] + b[tid];
}

// ---------------- generic tiled SGEMM: C = A(MxK) @ B(KxN) [+bias][relu][+res] ----------------
__global__ void k_gemm(const float* __restrict__ A, const float* __restrict__ Bm,
                       const float* __restrict__ bias, const float* __restrict__ res,
                       float* __restrict__ C, int N, int K, int relu){
  __shared__ __align__(16) float As[16][68];
  __shared__ __align__(16) float Bs[16][64];
  int tid = threadIdx.x;
  int m0 = blockIdx.y*64, n0 = blockIdx.x*64;
  int tx = tid & 15, ty = tid >> 4;
  int ka = tid & 15, ma = tid >> 4;
  int nb = tid & 63, kb = tid >> 6;
  float acc[4][4] = {};
  for (int k0 = 0; k0 < K; k0 += 16){
    #pragma unroll
    for (int i = 0; i < 4; i++)
      As[ka][ma + 16*i] = A[(size_t)(m0 + ma + 16*i)*K + k0 + ka];
    #pragma unroll
    for (int i = 0; i < 4; i++)
      Bs[kb + 4*i][nb] = Bm[(size_t)(k0 + kb + 4*i)*N + n0 + nb];
    __syncthreads();
    #pragma unroll
    for (int kk = 0; kk < 16; kk++){
      float4 av = *(const float4*)&As[kk][ty*4];
      float4 bv = *(const float4*)&Bs[kk][tx*4];
      float a[4] = {av.x, av.y, av.z, av.w};
      float b[4] = {bv.x, bv.y, bv.z, bv.w};
      #pragma unroll
      for (int i = 0; i < 4; i++)
        #pragma unroll
        for (int j = 0; j < 4; j++)
          acc[i][j] = fmaf(a[i], b[j], acc[i][j]);
    }
    __syncthreads();
  }
  #pragma unroll
  for (int i = 0; i < 4; i++){
    int m = m0 + ty*4 + i;
    #pragma unroll
    for (int j = 0; j < 4; j++){
      int n = n0 + tx*4 + j;
      float v = acc[i][j];
      if (bias) v += bias[n];
      if (relu) v = fmaxf(v, 0.0f);
      if (res)  v += res[(size_t)m*N + n];
      C[(size_t)m*N + n] = v;
    }
  }
}

// ---------------- scores[t][s] = SCALE * q[t]·k[s]  (lower-triangle tiles only) ----------------
__global__ void k_scores(){
  int st = blockIdx.x, tt = blockIdx.y, z = blockIdx.z;
  if (st > tt) return;
  int b = z >> 3, h = z & 7;
  int t0 = tt*64, s0 = st*64;
  __shared__ float Qs[64][33];
  __shared__ float Ks[64][33];
  int tid = threadIdx.x;
  int d = tid & 31, r = tid >> 5;
  const float* qb = g_qkv + (size_t)(b*Tq)*768 + h*32;
  const float* kb = qb + 256;
  #pragma unroll
  for (int i = 0; i < 8; i++){
    Qs[r + 8*i][d] = qb[(size_t)(t0 + r + 8*i)*768 + d];
    Ks[r + 8*i][d] = kb[(size_t)(s0 + r + 8*i)*768 + d];
  }
  __syncthreads();
  int tx = tid & 15, ty = tid >> 4;
  float acc[4][4] = {};
  #pragma unroll
  for (int kk = 0; kk < 32; kk++){
    float a[4], bb[4];
    #pragma unroll
    for (int i = 0; i < 4; i++) a[i]  = Qs[ty*4+i][kk];
    #pragma unroll
    for (int j = 0; j < 4; j++) bb[j] = Ks[tx*4+j][kk];
    #pragma unroll
    for (int i = 0; i < 4; i++)
      #pragma unroll
      for (int j = 0; j < 4; j++)
        acc[i][j] = fmaf(a[i], bb[j], acc[i][j]);
  }
  float* outp = g_attn + (size_t)z*Tq*Tq;
  #pragma unroll
  for (int i = 0; i < 4; i++){
    int t = t0 + ty*4 + i;
    #pragma unroll
    for (int j = 0; j < 4; j++){
      int s = s0 + tx*4 + j;
      outp[(size_t)t*Tq + s] = acc[i][j]*SCALE;
    }
  }
}

// ---------------- column softmax over query axis t (t >= s), in-place ----------------
// pass1: column max; pass2: write e = exp(x-m) (0 above diagonal inside diag tile), store 1/sum
__global__ void k_softmax(){
  int z = blockIdx.y;
  int s = blockIdx.x*256 + threadIdx.x;
  float* sc = g_attn + (size_t)z*Tq*Tq;
  float m = -1e30f;
  for (int t = s; t < Tq; t++)
    m = fmaxf(m, sc[(size_t)t*Tq + s]);
  float l = 0.f;
  int tb = s & ~63;   // start of the diagonal 64-tile: zero-fill t in [tb, s)
  for (int t = tb; t < Tq; t++){
    float v = 0.f;
    if (t >= s){
      v = fexp(sc[(size_t)t*Tq + s] - m);
      l += v;
    }
    sc[(size_t)t*Tq + s] = v;
  }
  g_linv[z*Tq + s] = 1.0f / l;
}

// ---------------- heads = attn @ (V / l),  xh = xn + heads ----------------
__global__ void k_av(){
  int tt = blockIdx.x, z = blockIdx.y;
  int b = z >> 3, h = z & 7;
  int t0 = tt*64;
  __shared__ float As2[64][65];
  __shared__ __align__(16) float Vs[64][32];
  int tid = threadIdx.x;
  int tx = tid & 7, ty = tid >> 3;       // tx -> 4 d's, ty -> 2 t's
  int sa = tid & 63, ra = tid >> 6;      // attn tile load
  int dv = tid & 31, rv = tid >> 5;      // v tile load
  float acc[2][4] = {};
  const float* attn = g_attn + (size_t)z*Tq*Tq;
  const float* vb   = g_qkv + (size_t)(b*Tq)*768 + 512 + h*32;
  const float* linv = g_linv + z*Tq;
  for (int st = 0; st <= tt; st++){
    int s0 = st*64;
    #pragma unroll
    for (int i = 0; i < 16; i++)
      As2[ra + 4*i][sa] = attn[(size_t)(t0 + ra + 4*i)*Tq + s0 + sa];
    #pragma unroll
    for (int i = 0; i < 8; i++){
      int srow = rv + 8*i;
      Vs[srow][dv] = vb[(size_t)(s0 + srow)*768 + dv] * linv[s0 + srow];
    }
    __syncthreads();
    #pragma unroll
    for (int ss = 0; ss < 64; ss++){
      float4 vv = *(const float4*)&Vs[ss][tx*4];
      float a0 = As2[ty*2    ][ss];
      float a1 = As2[ty*2 + 1][ss];
      acc[0][0] = fmaf(a0, vv.x, acc[0][0]);
      acc[0][1] = fmaf(a0, vv.y, acc[0][1]);
      acc[0][2] = fmaf(a0, vv.z, acc[0][2]);
      acc[0][3] = fmaf(a0, vv.w, acc[0][3]);
      acc[1][0] = fmaf(a1, vv.x, acc[1][0]);
      acc[1][1] = fmaf(a1, vv.y, acc[1][1]);
      acc[1][2] = fmaf(a1, vv.z, acc[1][2]);
      acc[1][3] = fmaf(a1, vv.w, acc[1][3]);
    }
    __syncthreads();
  }
  #pragma unroll
  for (int i = 0; i < 2; i++){
    int t = t0 + ty*2 + i;
    size_t base = (size_t)(b*Tq + t)*Eq + h*32 + tx*4;
    #pragma unroll
    for (int j = 0; j < 4; j++)
      g_xh[base + j] = acc[i][j] + g_xn[base + j];
  }
}

// ---------------- host launch ----------------
static float* symaddr(const void* sym){
  void* p = nullptr;
  cudaGetSymbolAddress(&p, sym);
  return (float*)p;
}

extern "C" void kernel_launch(void* const* d_in, const int* in_sizes, int n_in,
                              void* d_out, int out_size){
  (void)in_sizes; (void)n_in; (void)out_size;
  const float* x     = (const float*)d_in[0];
  const float* wq    = (const float*)d_in[1];
  const float* wk    = (const float*)d_in[2];
  const float* wv    = (const float*)d_in[3];
  const float* w_lin = (const float*)d_in[4];
  const float* b_lin = (const float*)d_in[5];
  const float* g1    = (const float*)d_in[6];
  const float* beta1 = (const float*)d_in[7];
  const float* g2    = (const float*)d_in[8];
  const float* beta2 = (const float*)d_in[9];
  const float* w_f1  = (const float*)d_in[10];
  const float* b_f1  = (const float*)d_in[11];
  const float* w_f2  = (const float*)d_in[12];
  const float* b_f2  = (const float*)d_in[13];
  float* out = (float*)d_out;

  float* xn  = symaddr(g_xn);
  float* qkv = symaddr(g_qkv);
  float* xh  = symaddr(g_xh);
  float* xl  = symaddr(g_xl);
  float* x2  = symaddr(g_x2);
  float* h1  = symaddr(g_h1);
  float* wp  = symaddr(g_wpack);

  // 1. pack qkv weights
  k_pack<<<256, 256>>>(wq, wk, wv);
  // 2. LN1
  k_ln<<<BT, 256>>>(x, g1, beta1, xn);
  // 3. qkv = xn @ wpack  (16384 x 768)
  k_gemm<<<dim3(768/64, BT/64), 256>>>(xn, wp, nullptr, nullptr, qkv, 768, Eq, 0);
  // 4. scores (causal tiles)
  k_scores<<<dim3(Tq/64, Tq/64, BHq), 256>>>();
  // 5. column softmax (over query axis)
  k_softmax<<<dim3(Tq/256, BHq), 256>>>();
  // 6. heads = attn @ V/l ; xh = xn + heads
  k_av<<<dim3(Tq/64, BHq), 256>>>();
  // 7. xl = xh @ w_lin + b_lin
  k_gemm<<<dim3(Eq/64, BT/64), 256>>>(xh, w_lin, b_lin, nullptr, xl, Eq, Eq, 0);
  // 8. LN2
  k_ln<<<BT, 256>>>(xl, g2, beta2, x2);
  // 9. h1 = relu(x2 @ w_f1 + b_f1)
  k_gemm<<<dim3(Fq/64, BT/64), 256>>>(x2, w_f1, b_f1, nullptr, h1, Fq, Eq, 1);
  // 10. out = h1 @ w_f2 + b_f2 + x2
  k_gemm<<<dim3(Eq/64, BT/64), 256>>>(h1, w_f2, b_f2, x2, out, Eq, Fq, 0);
}

// round 2
// speedup vs baseline: 2.4601x; 2.4601x over previous
#include <cuda_runtime.h>
#include <cuda_fp16.h>

#define Tq 2048
#define Eq 256
#define BT 16384        /* 8*2048 */
#define BHq 64
#define SCALE 0.0625f   /* E^-0.5 */

// ---------------- scratch ----------------
__device__ float g_xn[BT*Eq];
__device__ float g_qkv[BT*768];                 // cols: 0..255 q, 256..511 k, 512..767 v; col=h*32+d
__device__ float g_attn[(size_t)BHq*Tq*Tq];     // 1 GB raw scaled scores
__device__ __half g_eh[(size_t)BHq*Tq*Tq];      // 0.5 GB exp values
__device__ unsigned g_m[BHq*Tq];                // encoded column max
__device__ float g_linv[BHq*Tq];                // 1/column-sum
__device__ float g_xh[BT*Eq];
__device__ float g_xl[BT*Eq];
__device__ float g_x2[BT*Eq];
__device__ float g_h1[(size_t)BT*1024];
__device__ float g_wpack[Eq*768];

// ---------------- helpers ----------------
__device__ __forceinline__ unsigned f2tf(float f){
  unsigned r; asm("cvt.rna.tf32.f32 %0, %1;" : "=r"(r) : "f"(f)); return r;
}
__device__ __forceinline__ void mma_tf32(float* c, const unsigned* a, const unsigned* b){
  asm volatile("mma.sync.aligned.m16n8k8.row.col.f32.tf32.tf32.f32 "
               "{%0,%1,%2,%3}, {%4,%5,%6,%7}, {%8,%9}, {%0,%1,%2,%3};\n"
               : "+f"(c[0]), "+f"(c[1]), "+f"(c[2]), "+f"(c[3])
               : "r"(a[0]), "r"(a[1]), "r"(a[2]), "r"(a[3]), "r"(b[0]), "r"(b[1]));
}
__device__ __forceinline__ unsigned encf(float f){
  int b = __float_as_int(f);
  return b >= 0 ? ((unsigned)b | 0x80000000u) : ~(unsigned)b;
}
__device__ __forceinline__ float decf(unsigned u){
  return (u & 0x80000000u) ? __int_as_float((int)(u & 0x7fffffffu))
                           : __int_as_float(~(int)u);
}
__device__ __forceinline__ float fexp(float x){
  float t = x * 1.4426950408889634f;
  t = fmaxf(t, -126.0f);
  int ei = __float2int_rd(t);
  float f = t - (float)ei;
  float p =            1.5403530e-4f;
  p = fmaf(p, f, 1.3333558e-3f);
  p = fmaf(p, f, 9.6181291e-3f);
  p = fmaf(p, f, 5.5504109e-2f);
  p = fmaf(p, f, 2.4022651e-1f);
  p = fmaf(p, f, 6.9314718e-1f);
  p = fmaf(p, f, 1.0f);
  return __int_as_float((ei + 127) << 23) * p;
}

// ---------------- weight packing ----------------
__global__ void k_pack(const float* __restrict__ wq, const float* __restrict__ wk,
                       const float* __restrict__ wv){
  int idx = blockIdx.x*256 + threadIdx.x;
  if (idx >= Eq*Eq) return;
  int e = idx >> 8, c = idx & 255;
  int h = c >> 5, d = c & 31;
  int src = h*Eq*32 + e*32 + d;
  g_wpack[e*768 +       c] = wq[src];
  g_wpack[e*768 + 256 + c] = wk[src];
  g_wpack[e*768 + 512 + c] = wv[src];
}

__global__ void k_initm(){
  int i = blockIdx.x*256 + threadIdx.x;
  if (i < BHq*Tq) g_m[i] = 0u;
}

// ---------------- LayerNorm ----------------
__global__ void k_ln(const float* __restrict__ in, const float* __restrict__ g,
                     const float* __restrict__ b, float* __restrict__ out){
  int row = blockIdx.x, tid = threadIdx.x;
  float x = in[(size_t)row*Eq + tid];
  float s = x, s2 = x*x;
  #pragma unroll
  for (int o = 16; o > 0; o >>= 1){
    s  += __shfl_xor_sync(0xffffffffu, s,  o);
    s2 += __shfl_xor_sync(0xffffffffu, s2, o);
  }
  __shared__ float ws[8], ws2[8];
  __shared__ float smean, sinv;
  if ((tid & 31) == 0){ ws[tid>>5] = s; ws2[tid>>5] = s2; }
  __syncthreads();
  if (tid == 0){
    float t = 0.f, t2 = 0.f;
    #pragma unroll
    for (int i = 0; i < 8; i++){ t += ws[i]; t2 += ws2[i]; }
    float mean = t * (1.0f/Eq);
    float var  = t2 * (1.0f/Eq) - mean*mean;
    smean = mean;
    sinv  = rsqrtf(var + 1e-5f);
  }
  __syncthreads();
  out[(size_t)row*Eq + tid] = (x - smean)*sinv*g[tid] + b[tid];
}

// ---------------- TF32 GEMM: C(MxN) = A(MxK) @ B(KxN) [+bias][relu][+res] ----------------
// block tile 128x64, 256 threads (8 warps: 4x2 of 32x32 warp tiles)
__global__ __launch_bounds__(256) void k_mm(
    const float* __restrict__ A, const float* __restrict__ Bm,
    const float* __restrict__ bias, const float* __restrict__ res,
    float* __restrict__ C, int N, int K, int relu)
{
  __shared__ unsigned As[128][36];
  __shared__ unsigned Bs[32][72];
  int tid = threadIdx.x;
  int lane = tid & 31, warp = tid >> 5;
  int wm = warp >> 1, wn = warp & 1;
  int m0 = blockIdx.y*128, n0 = blockIdx.x*64;
  int ar = tid >> 3, ac = (tid & 7) * 4;
  int br = tid >> 4, bc = (tid & 15) * 4;
  float acc[2][4][4] = {};

  for (int k0 = 0; k0 < K; k0 += 32){
    #pragma unroll
    for (int i = 0; i < 4; i++){
      float4 v = *(const float4*)&A[(size_t)(m0 + ar + 32*i)*K + k0 + ac];
      As[ar+32*i][ac  ] = f2tf(v.x);
      As[ar+32*i][ac+1] = f2tf(v.y);
      As[ar+32*i][ac+2] = f2tf(v.z);
      As[ar+32*i][ac+3] = f2tf(v.w);
    }
    #pragma unroll
    for (int i = 0; i < 2; i++){
      float4 v = *(const float4*)&Bm[(size_t)(k0 + br + 16*i)*N + n0 + bc];
      Bs[br+16*i][bc  ] = f2tf(v.x);
      Bs[br+16*i][bc+1] = f2tf(v.y);
      Bs[br+16*i][bc+2] = f2tf(v.z);
      Bs[br+16*i][bc+3] = f2tf(v.w);
    }
    __syncthreads();
    #pragma unroll
    for (int ks = 0; ks < 4; ks++){
      int k8 = ks*8;
      unsigned a[2][4], b[4][2];
      #pragma unroll
      for (int mi = 0; mi < 2; mi++){
        int row = wm*32 + mi*16 + (lane>>2);
        a[mi][0] = As[row  ][k8 +     (lane&3)];
        a[mi][1] = As[row+8][k8 +     (lane&3)];
        a[mi][2] = As[row  ][k8 + 4 + (lane&3)];
        a[mi][3] = As[row+8][k8 + 4 + (lane&3)];
      }
      #pragma unroll
      for (int ni = 0; ni < 4; ni++){
        int col = wn*32 + ni*8 + (lane>>2);
        b[ni][0] = Bs[k8 +     (lane&3)][col];
        b[ni][1] = Bs[k8 + 4 + (lane&3)][col];
      }
      #pragma unroll
      for (int mi = 0; mi < 2; mi++)
        #pragma unroll
        for (int ni = 0; ni < 4; ni++)
          mma_tf32(acc[mi][ni], a[mi], b[ni]);
    }
    __syncthreads();
  }
  // epilogue
  #pragma unroll
  for (int mi = 0; mi < 2; mi++){
    #pragma unroll
    for (int ni = 0; ni < 4; ni++){
      #pragma unroll
      for (int half = 0; half < 2; half++){
        int r = m0 + wm*32 + mi*16 + (lane>>2) + half*8;
        int c = n0 + wn*32 + ni*8 + 2*(lane&3);
        float v0 = acc[mi][ni][half*2  ];
        float v1 = acc[mi][ni][half*2+1];
        if (bias){ v0 += bias[c]; v1 += bias[c+1]; }
        if (relu){ v0 = fmaxf(v0, 0.f); v1 = fmaxf(v1, 0.f); }
        if (res){
          float2 rv = *(const float2*)&res[(size_t)r*N + c];
          v0 += rv.x; v1 += rv.y;
        }
        float2 o; o.x = v0; o.y = v1;
        *(float2*)&C[(size_t)r*N + c] = o;
      }
    }
  }
}

// ---------------- scores: 128t x 64s tiles, TF32 mma, fused column atomicMax ----------------
__global__ __launch_bounds__(256) void k_scores(){
  int st = blockIdx.x, tt = blockIdx.y, z = blockIdx.z;
  int s0 = st*64, t0 = tt*128;
  if (s0 >= t0 + 128) return;
  int b = z >> 3, h = z & 7;
  int tid = threadIdx.x, lane = tid & 31, warp = tid >> 5;
  int wm = warp >> 1, wn = warp & 1;

  __shared__ __align__(16) char sb[128*72*4];
  unsigned (*Qs)[36] = (unsigned(*)[36])sb;           // 128 x 36
  unsigned (*Ks)[36] = (unsigned(*)[36])(sb + 128*36*4); // 64 x 36 (s-major, d cols)
  float    (*Cs)[72] = (float(*)[72])sb;              // reused after compute
  __shared__ float red[4][64];

  const float* qb = g_qkv + (size_t)(b*Tq)*768 + h*32;
  const float* kb = qb + 256;
  int r = tid >> 3, c4 = (tid & 7) * 4;
  #pragma unroll
  for (int i = 0; i < 4; i++){
    float4 v = *(const float4*)&qb[(size_t)(t0 + r + 32*i)*768 + c4];
    Qs[r+32*i][c4] = f2tf(v.x); Qs[r+32*i][c4+1] = f2tf(v.y);
    Qs[r+32*i][c4+2] = f2tf(v.z); Qs[r+32*i][c4+3] = f2tf(v.w);
  }
  #pragma unroll
  for (int i = 0; i < 2; i++){
    float4 v = *(const float4*)&kb[(size_t)(s0 + r + 32*i)*768 + c4];
    Ks[r+32*i][c4] = f2tf(v.x); Ks[r+32*i][c4+1] = f2tf(v.y);
    Ks[r+32*i][c4+2] = f2tf(v.z); Ks[r+32*i][c4+3] = f2tf(v.w);
  }
  __syncthreads();

  float acc[2][4][4] = {};
  #pragma unroll
  for (int ks = 0; ks < 4; ks++){
    int k8 = ks*8;
    unsigned a[2][4], bfr[4][2];
    #pragma unroll
    for (int mi = 0; mi < 2; mi++){
      int row = wm*32 + mi*16 + (lane>>2);
      a[mi][0] = Qs[row  ][k8 +     (lane&3)];
      a[mi][1] = Qs[row+8][k8 +     (lane&3)];
      a[mi][2] = Qs[row  ][k8 + 4 + (lane&3)];
      a[mi][3] = Qs[row+8][k8 + 4 + (lane&3)];
    }
    #pragma unroll
    for (int ni = 0; ni < 4; ni++){
      int col = wn*32 + ni*8 + (lane>>2);     // s index
      bfr[ni][0] = Ks[col][k8 +     (lane&3)];
      bfr[ni][1] = Ks[col][k8 + 4 + (lane&3)];
    }
    #pragma unroll
    for (int mi = 0; mi < 2; mi++)
      #pragma unroll
      for (int ni = 0; ni < 4; ni++)
        mma_tf32(acc[mi][ni], a[mi], bfr[ni]);
  }
  __syncthreads();      // done reading Qs/Ks; reuse as Cs

  #pragma unroll
  for (int mi = 0; mi < 2; mi++)
    #pragma unroll
    for (int ni = 0; ni < 4; ni++)
      #pragma unroll
      for (int half = 0; half < 2; half++){
        int rr = wm*32 + mi*16 + (lane>>2) + half*8;
        int cc = wn*32 + ni*8 + 2*(lane&3);
        Cs[rr][cc  ] = acc[mi][ni][half*2  ] * SCALE;
        Cs[rr][cc+1] = acc[mi][ni][half*2+1] * SCALE;
      }
  __syncthreads();

  size_t zb = (size_t)z*Tq*Tq;
  #pragma unroll
  for (int i = 0; i < 8; i++){
    int lin = tid + 256*i;
    int row = lin >> 4, cc = (lin & 15) * 4;
    float4 v = *(float4*)&Cs[row][cc];
    *(float4*)&g_attn[zb + (size_t)(t0+row)*Tq + s0 + cc] = v;
  }
  // per-column max -> atomicMax (includes a few t<s rows; harmless shift)
  int c = tid & 63, rg = tid >> 6;
  float mx = -1e30f;
  #pragma unroll
  for (int i = 0; i < 32; i++) mx = fmaxf(mx, Cs[rg + 4*i][c]);
  red[rg][c] = mx;
  __syncthreads();
  if (rg == 0){
    float m = fmaxf(fmaxf(red[0][c], red[1][c]), fmaxf(red[2][c], red[3][c]));
    atomicMax(&g_m[z*Tq + s0 + c], encf(m));
  }
}

// ---------------- column softmax: e = exp(sc - m), column sums, store fp16 ----------------
__global__ void k_colsoftmax(){
  int z = blockIdx.y;
  int s0 = blockIdx.x * 64;
  int tid = threadIdx.x;
  int c = tid & 63, rg = tid >> 6;
  int cg = s0 + c;
  size_t zb = (size_t)z*Tq*Tq;
  float m = decf(g_m[z*Tq + cg]);
  int tbeg = (s0 >> 7) << 7;    // 128-aligned tile start covering diagonal
  float sum = 0.f;
  for (int t = tbeg + rg; t < Tq; t += 4){
    float e = 0.f;
    if (t >= cg){
      float sc = g_attn[zb + (size_t)t*Tq + cg];
      e = fexp(sc - m);
      sum += e;
    }
    g_eh[zb + (size_t)t*Tq + cg] = __float2half_rn(e);
  }
  __shared__ float red[4][64];
  red[rg][c] = sum;
  __syncthreads();
  if (rg == 0){
    float tot = red[0][c] + red[1][c] + red[2][c] + red[3][c];
    g_linv[z*Tq + cg] = 1.0f / tot;
  }
}

// ---------------- AV: heads = e @ (V * linv), + xn residual. TF32 mma ----------------
// block tile 128t x 32d, 8 warps of 16x32
__global__ __launch_bounds__(256) void k_av(){
  int tt = blockIdx.x, z = blockIdx.y;
  int b = z >> 3, h = z & 7;
  int t0 = tt*128;
  int tid = threadIdx.x, lane = tid & 31, warp = tid >> 5;

  __shared__ unsigned At[128][36];
  __shared__ unsigned Vs[32][36];

  size_t zb = (size_t)z*Tq*Tq;
  const float* vb = g_qkv + (size_t)(b*Tq)*768 + 512 + h*32;
  const float* linv = g_linv + z*Tq;

  float acc[4][4] = {};
  int nchunk = 4*(tt+1);
  int vr = tid >> 3, vc4 = (tid & 7)*4;
  for (int ch = 0; ch < nchunk; ch++){
    int s0 = ch*32;
    #pragma unroll
    for (int i = 0; i < 8; i++){
      int lin = tid + 256*i;
      int row = lin >> 4, c2 = lin & 15;
      __half2 h2 = *(const __half2*)&g_eh[zb + (size_t)(t0+row)*Tq + s0 + 2*c2];
      float2 f = __half22float2(h2);
      At[row][2*c2  ] = f2tf(f.x);
      At[row][2*c2+1] = f2tf(f.y);
    }
    {
      float li = linv[s0 + vr];
      float4 v = *(const float4*)&vb[(size_t)(s0 + vr)*768 + vc4];
      Vs[vr][vc4  ] = f2tf(v.x * li);
      Vs[vr][vc4+1] = f2tf(v.y * li);
      Vs[vr][vc4+2] = f2tf(v.z * li);
      Vs[vr][vc4+3] = f2tf(v.w * li);
    }
    __syncthreads();
    #pragma unroll
    for (int ks = 0; ks < 4; ks++){
      int k8 = ks*8;
      unsigned a[4], bf[4][2];
      int row = warp*16 + (lane>>2);
      a[0] = At[row  ][k8 +     (lane&3)];
      a[1] = At[row+8][k8 +     (lane&3)];
      a[2] = At[row  ][k8 + 4 + (lane&3)];
      a[3] = At[row+8][k8 + 4 + (lane&3)];
      #pragma unroll
      for (int ni = 0; ni < 4; ni++){
        int col = ni*8 + (lane>>2);
        bf[ni][0] = Vs[k8 +     (lane&3)][col];
        bf[ni][1] = Vs[k8 + 4 + (lane&3)][col];
      }
      #pragma unroll
      for (int ni = 0; ni < 4; ni++)
        mma_tf32(acc[ni], a, bf[ni]);
    }
    __syncthreads();
  }
  #pragma unroll
  for (int ni = 0; ni < 4; ni++){
    #pragma unroll
    for (int half = 0; half < 2; half++){
      int t = t0 + warp*16 + (lane>>2) + half*8;
      int cc = h*32 + ni*8 + 2*(lane&3);
      size_t base = (size_t)(b*Tq + t)*Eq + cc;
      float2 rv = *(const float2*)&g_xn[base];
      float2 o;
      o.x = acc[ni][half*2  ] + rv.x;
      o.y = acc[ni][half*2+1] + rv.y;
      *(float2*)&g_xh[base] = o;
    }
  }
}

// ---------------- host ----------------
static float* symaddr(const void* sym){
  void* p = nullptr;
  cudaGetSymbolAddress(&p, sym);
  return (float*)p;
}

extern "C" void kernel_launch(void* const* d_in, const int* in_sizes, int n_in,
                              void* d_out, int out_size){
  (void)in_sizes; (void)n_in; (void)out_size;
  const float* x     = (const float*)d_in[0];
  const float* wq    = (const float*)d_in[1];
  const float* wk    = (const float*)d_in[2];
  const float* wv    = (const float*)d_in[3];
  const float* w_lin = (const float*)d_in[4];
  const float* b_lin = (const float*)d_in[5];
  const float* g1    = (const float*)d_in[6];
  const float* beta1 = (const float*)d_in[7];
  const float* g2    = (const float*)d_in[8];
  const float* beta2 = (const float*)d_in[9];
  const float* w_f1  = (const float*)d_in[10];
  const float* b_f1  = (const float*)d_in[11];
  const float* w_f2  = (const float*)d_in[12];
  const float* b_f2  = (const float*)d_in[13];
  float* out = (float*)d_out;

  float* xn  = symaddr(g_xn);
  float* qkv = symaddr(g_qkv);
  float* xh  = symaddr(g_xh);
  float* xl  = symaddr(g_xl);
  float* x2  = symaddr(g_x2);
  float* h1  = symaddr(g_h1);
  float* wp  = symaddr(g_wpack);

  k_pack<<<256, 256>>>(wq, wk, wv);
  k_initm<<<512, 256>>>();
  k_ln<<<BT, 256>>>(x, g1, beta1, xn);
  k_mm<<<dim3(768/64, BT/128), 256>>>(xn, wp, nullptr, nullptr, qkv, 768, Eq, 0);
  k_scores<<<dim3(32, 16, 64), 256>>>();
  k_colsoftmax<<<dim3(32, 64), 256>>>();
  k_av<<<dim3(16, 64), 256>>>();
  k_mm<<<dim3(Eq/64, BT/128), 256>>>(xh, w_lin, b_lin, nullptr, xl, Eq, Eq, 0);
  k_ln<<<BT, 256>>>(xl, g2, beta2, x2);
  k_mm<<<dim3(1024/64, BT/128), 256>>>(x2, w_f1, b_f1, nullptr, h1, 1024, Eq, 1);
  k_mm<<<dim3(Eq/64, BT/128), 256>>>(h1, w_f2, b_f2, x2, out, Eq, 1024, 0);
}

// round 3
// speedup vs baseline: 4.2868x; 1.7425x over previous
#include <cuda_runtime.h>

#define Tq 2048
#define Eq 256
#define BT 16384        /* 8*2048 */
#define BHq 64
#define SCALE 0.0625f   /* E^-0.5, folded into wq at pack time */

// ---------------- scratch ----------------
__device__ float g_xn[BT*Eq];
__device__ float g_qkv[BT*768];     // cols: 0..255 q(prescaled), 256..511 k, 512..767 v; col=h*32+d
__device__ float g_linv[BHq*Tq];    // 1 / column-sum of exp
__device__ float g_xh[BT*Eq];
__device__ float g_xl[BT*Eq];
__device__ float g_x2[BT*Eq];
__device__ float g_h1[(size_t)BT*1024];
__device__ float g_wpack[Eq*768];

// ---------------- helpers ----------------
__device__ __forceinline__ unsigned f2tf(float f){
  unsigned r; asm("cvt.rna.tf32.f32 %0, %1;" : "=r"(r) : "f"(f)); return r;
}
__device__ __forceinline__ void mma_tf32(float* c, const unsigned* a, const unsigned* b){
  asm volatile("mma.sync.aligned.m16n8k8.row.col.f32.tf32.tf32.f32 "
               "{%0,%1,%2,%3}, {%4,%5,%6,%7}, {%8,%9}, {%0,%1,%2,%3};\n"
               : "+f"(c[0]), "+f"(c[1]), "+f"(c[2]), "+f"(c[3])
               : "r"(a[0]), "r"(a[1]), "r"(a[2]), "r"(a[3]), "r"(b[0]), "r"(b[1]));
}

// ---------------- weight packing (SCALE folded into wq) ----------------
__global__ void k_pack(const float* __restrict__ wq, const float* __restrict__ wk,
                       const float* __restrict__ wv){
  int idx = blockIdx.x*256 + threadIdx.x;
  if (idx >= Eq*Eq) return;
  int e = idx >> 8, c = idx & 255;
  int h = c >> 5, d = c & 31;
  int src = h*Eq*32 + e*32 + d;
  g_wpack[e*768 +       c] = wq[src] * SCALE;
  g_wpack[e*768 + 256 + c] = wk[src];
  g_wpack[e*768 + 512 + c] = wv[src];
}

// ---------------- LayerNorm ----------------
__global__ void k_ln(const float* __restrict__ in, const float* __restrict__ g,
                     const float* __restrict__ b, float* __restrict__ out){
  int row = blockIdx.x, tid = threadIdx.x;
  float x = in[(size_t)row*Eq + tid];
  float s = x, s2 = x*x;
  #pragma unroll
  for (int o = 16; o > 0; o >>= 1){
    s  += __shfl_xor_sync(0xffffffffu, s,  o);
    s2 += __shfl_xor_sync(0xffffffffu, s2, o);
  }
  __shared__ float ws[8], ws2[8];
  __shared__ float smean, sinv;
  if ((tid & 31) == 0){ ws[tid>>5] = s; ws2[tid>>5] = s2; }
  __syncthreads();
  if (tid == 0){
    float t = 0.f, t2 = 0.f;
    #pragma unroll
    for (int i = 0; i < 8; i++){ t += ws[i]; t2 += ws2[i]; }
    float mean = t * (1.0f/Eq);
    float var  = t2 * (1.0f/Eq) - mean*mean;
    smean = mean;
    sinv  = rsqrtf(var + 1e-5f);
  }
  __syncthreads();
  out[(size_t)row*Eq + tid] = (x - smean)*sinv*g[tid] + b[tid];
}

// ---------------- TF32 GEMM: C(MxN) = A(MxK) @ B(KxN) [+bias][relu][+res] ----------------
__global__ __launch_bounds__(256) void k_mm(
    const float* __restrict__ A, const float* __restrict__ Bm,
    const float* __restrict__ bias, const float* __restrict__ res,
    float* __restrict__ C, int N, int K, int relu)
{
  __shared__ unsigned As[128][36];
  __shared__ unsigned Bs[32][72];
  int tid = threadIdx.x;
  int lane = tid & 31, warp = tid >> 5;
  int wm = warp >> 1, wn = warp & 1;
  int m0 = blockIdx.y*128, n0 = blockIdx.x*64;
  int ar = tid >> 3, ac = (tid & 7) * 4;
  int br = tid >> 4, bc = (tid & 15) * 4;
  float acc[2][4][4] = {};

  for (int k0 = 0; k0 < K; k0 += 32){
    #pragma unroll
    for (int i = 0; i < 4; i++){
      float4 v = *(const float4*)&A[(size_t)(m0 + ar + 32*i)*K + k0 + ac];
      As[ar+32*i][ac  ] = f2tf(v.x);
      As[ar+32*i][ac+1] = f2tf(v.y);
      As[ar+32*i][ac+2] = f2tf(v.z);
      As[ar+32*i][ac+3] = f2tf(v.w);
    }
    #pragma unroll
    for (int i = 0; i < 2; i++){
      float4 v = *(const float4*)&Bm[(size_t)(k0 + br + 16*i)*N + n0 + bc];
      Bs[br+16*i][bc  ] = f2tf(v.x);
      Bs[br+16*i][bc+1] = f2tf(v.y);
      Bs[br+16*i][bc+2] = f2tf(v.z);
      Bs[br+16*i][bc+3] = f2tf(v.w);
    }
    __syncthreads();
    #pragma unroll
    for (int ks = 0; ks < 4; ks++){
      int k8 = ks*8;
      unsigned a[2][4], b[4][2];
      #pragma unroll
      for (int mi = 0; mi < 2; mi++){
        int row = wm*32 + mi*16 + (lane>>2);
        a[mi][0] = As[row  ][k8 +     (lane&3)];
        a[mi][1] = As[row+8][k8 +     (lane&3)];
        a[mi][2] = As[row  ][k8 + 4 + (lane&3)];
        a[mi][3] = As[row+8][k8 + 4 + (lane&3)];
      }
      #pragma unroll
      for (int ni = 0; ni < 4; ni++){
        int col = wn*32 + ni*8 + (lane>>2);
        b[ni][0] = Bs[k8 +     (lane&3)][col];
        b[ni][1] = Bs[k8 + 4 + (lane&3)][col];
      }
      #pragma unroll
      for (int mi = 0; mi < 2; mi++)
        #pragma unroll
        for (int ni = 0; ni < 4; ni++)
          mma_tf32(acc[mi][ni], a[mi], b[ni]);
    }
    __syncthreads();
  }
  #pragma unroll
  for (int mi = 0; mi < 2; mi++){
    #pragma unroll
    for (int ni = 0; ni < 4; ni++){
      #pragma unroll
      for (int half = 0; half < 2; half++){
        int r = m0 + wm*32 + mi*16 + (lane>>2) + half*8;
        int c = n0 + wn*32 + ni*8 + 2*(lane&3);
        float v0 = acc[mi][ni][half*2  ];
        float v1 = acc[mi][ni][half*2+1];
        if (bias){ v0 += bias[c]; v1 += bias[c+1]; }
        if (relu){ v0 = fmaxf(v0, 0.f); v1 = fmaxf(v1, 0.f); }
        if (res){
          float2 rv = *(const float2*)&res[(size_t)r*N + c];
          v0 += rv.x; v1 += rv.y;
        }
        float2 o; o.x = v0; o.y = v1;
        *(float2*)&C[(size_t)r*N + c] = o;
      }
    }
  }
}

// ---------------- pass 1: per-column sum of exp(scores) over t >= s ----------------
// block: 64 s-columns of one (b,h); warps stride t-tiles (16 rows each); no max needed (m=0)
__global__ __launch_bounds__(256) void k_colsum(){
  int s0 = blockIdx.x * 64;
  int z = blockIdx.y;
  int b = z >> 3, h = z & 7;
  int tid = threadIdx.x, lane = tid & 31, warp = tid >> 5;
  int r = lane >> 2, c = lane & 3;
  __shared__ unsigned Ks[64*36];
  __shared__ float red[8][64];
  const float* qb = g_qkv + (size_t)(b*Tq)*768 + h*32;
  const float* kb = qb + 256;
  {
    int kr = tid >> 3, kc = (tid & 7)*4;
    #pragma unroll
    for (int i = 0; i < 2; i++){
      int row = kr + 32*i;
      float4 v = *(const float4*)&kb[(size_t)(s0 + row)*768 + kc];
      unsigned* p = &Ks[row*36 + kc];
      p[0] = f2tf(v.x); p[1] = f2tf(v.y); p[2] = f2tf(v.z); p[3] = f2tf(v.w);
    }
  }
  __syncthreads();
  float lacc[8][2];
  #pragma unroll
  for (int i = 0; i < 8; i++){ lacc[i][0] = 0.f; lacc[i][1] = 0.f; }

  for (int t0 = s0 + warp*16; t0 < Tq; t0 += 128){
    unsigned a[4][4];
    const float* q0 = qb + (size_t)(t0 + r)*768;
    const float* q1 = q0 + 8*768;
    #pragma unroll
    for (int ks = 0; ks < 4; ks++){
      a[ks][0] = f2tf(__ldg(q0 + ks*8 + c));
      a[ks][1] = f2tf(__ldg(q1 + ks*8 + c));
      a[ks][2] = f2tf(__ldg(q0 + ks*8 + 4 + c));
      a[ks][3] = f2tf(__ldg(q1 + ks*8 + 4 + c));
    }
    bool dg = (t0 < s0 + 64);
    #pragma unroll
    for (int ni = 0; ni < 8; ni++){
      float acc[4] = {0.f, 0.f, 0.f, 0.f};
      #pragma unroll
      for (int ks = 0; ks < 4; ks++){
        unsigned bf[2];
        bf[0] = Ks[(ni*8 + r)*36 + ks*8 + c];
        bf[1] = Ks[(ni*8 + r)*36 + ks*8 + 4 + c];
        mma_tf32(acc, a[ks], bf);
      }
      #pragma unroll
      for (int v = 0; v < 4; v++){
        float e = __expf(acc[v]);
        if (dg){
          int tg = t0 + r + (v>>1)*8;
          int sg = s0 + ni*8 + 2*c + (v&1);
          if (tg < sg) e = 0.f;
        }
        lacc[ni][v&1] += e;
      }
    }
  }
  #pragma unroll
  for (int ni = 0; ni < 8; ni++)
    #pragma unroll
    for (int j = 0; j < 2; j++){
      float v = lacc[ni][j];
      v += __shfl_xor_sync(0xffffffffu, v, 4);
      v += __shfl_xor_sync(0xffffffffu, v, 8);
      v += __shfl_xor_sync(0xffffffffu, v, 16);
      lacc[ni][j] = v;
    }
  if (r == 0){
    #pragma unroll
    for (int ni = 0; ni < 8; ni++){
      red[warp][ni*8 + 2*c    ] = lacc[ni][0];
      red[warp][ni*8 + 2*c + 1] = lacc[ni][1];
    }
  }
  __syncthreads();
  if (tid < 64){
    float tot = 0.f;
    #pragma unroll
    for (int w = 0; w < 8; w++) tot += red[w][tid];
    g_linv[z*Tq + s0 + tid] = 1.0f / tot;
  }
}

// ---------------- pass 2: fused scores-recompute + exp + AV + residual ----------------
// t-block 128 rows; loop s-tiles of 64; e stashed as tf32 in smem; V has 1/l folded in
#define AV_SMEM 72704
__global__ __launch_bounds__(256) void k_av(){
  extern __shared__ unsigned sm[];
  unsigned* Qs = sm;            // [128][36]
  unsigned* Ks = sm + 4608;     // [64][36]
  unsigned* Vs = sm + 6912;     // [64][40]
  unsigned* Et = sm + 9472;     // [128][68]
  int tt = 15 - blockIdx.x;     // heavy blocks first
  int z = blockIdx.y;
  int b = z >> 3, h = z & 7;
  int t0 = tt*128;
  int tid = threadIdx.x, lane = tid & 31, warp = tid >> 5;
  int r = lane >> 2, c = lane & 3;
  int wm = warp >> 1, wn = warp & 1;
  const float* qb = g_qkv + (size_t)(b*Tq)*768 + h*32;
  const float* kb = qb + 256;
  const float* vb = qb + 512;
  const float* linv = g_linv + z*Tq;

  {
    int qr = tid >> 3, qc = (tid & 7)*4;
    #pragma unroll
    for (int i = 0; i < 4; i++){
      int row = qr + 32*i;
      float4 v = *(const float4*)&qb[(size_t)(t0 + row)*768 + qc];
      unsigned* p = &Qs[row*36 + qc];
      p[0] = f2tf(v.x); p[1] = f2tf(v.y); p[2] = f2tf(v.z); p[3] = f2tf(v.w);
    }
  }
  float av[4][4] = {};
  for (int s0 = 0; s0 <= t0 + 64; s0 += 64){
    __syncthreads();
    {
      int kr = tid >> 3, kc = (tid & 7)*4;
      #pragma unroll
      for (int i = 0; i < 2; i++){
        int row = kr + 32*i;
        float4 kv = *(const float4*)&kb[(size_t)(s0 + row)*768 + kc];
        unsigned* p = &Ks[row*36 + kc];
        p[0] = f2tf(kv.x); p[1] = f2tf(kv.y); p[2] = f2tf(kv.z); p[3] = f2tf(kv.w);
        float li = linv[s0 + row];
        float4 vv = *(const float4*)&vb[(size_t)(s0 + row)*768 + kc];
        unsigned* pv = &Vs[row*40 + kc];
        pv[0] = f2tf(vv.x*li); pv[1] = f2tf(vv.y*li);
        pv[2] = f2tf(vv.z*li); pv[3] = f2tf(vv.w*li);
      }
    }
    __syncthreads();
    // scores: 128t x 64s, warp tile 32x32
    float sc[2][4][4] = {};
    #pragma unroll
    for (int ks = 0; ks < 4; ks++){
      int k8 = ks*8;
      unsigned a[2][4], bf[4][2];
      #pragma unroll
      for (int mi = 0; mi < 2; mi++){
        int row = wm*32 + mi*16 + r;
        a[mi][0] = Qs[row*36     + k8 + c];
        a[mi][1] = Qs[(row+8)*36 + k8 + c];
        a[mi][2] = Qs[row*36     + k8 + 4 + c];
        a[mi][3] = Qs[(row+8)*36 + k8 + 4 + c];
      }
      #pragma unroll
      for (int ni = 0; ni < 4; ni++){
        int col = wn*32 + ni*8 + r;
        bf[ni][0] = Ks[col*36 + k8 + c];
        bf[ni][1] = Ks[col*36 + k8 + 4 + c];
      }
      #pragma unroll
      for (int mi = 0; mi < 2; mi++)
        #pragma unroll
        for (int ni = 0; ni < 4; ni++)
          mma_tf32(sc[mi][ni], a[mi], bf[ni]);
    }
    bool dg = (s0 + 63 > t0);
    #pragma unroll
    for (int mi = 0; mi < 2; mi++)
      #pragma unroll
      for (int ni = 0; ni < 4; ni++)
        #pragma unroll
        for (int hf = 0; hf < 2; hf++){
          int rr = wm*32 + mi*16 + r + hf*8;
          int cc = wn*32 + ni*8 + 2*c;
          float e0 = __expf(sc[mi][ni][hf*2  ]);
          float e1 = __expf(sc[mi][ni][hf*2+1]);
          if (dg){
            int tg = t0 + rr;
            if (tg < s0 + cc    ) e0 = 0.f;
            if (tg < s0 + cc + 1) e1 = 0.f;
          }
          Et[rr*68 + cc    ] = f2tf(e0);
          Et[rr*68 + cc + 1] = f2tf(e1);
        }
    __syncthreads();
    // AV: warp handles 16 t-rows x 32 d, k = 64
    #pragma unroll
    for (int ks = 0; ks < 8; ks++){
      int k8 = ks*8;
      unsigned a[4], bf[4][2];
      int row = warp*16 + r;
      a[0] = Et[row*68     + k8 + c];
      a[1] = Et[(row+8)*68 + k8 + c];
      a[2] = Et[row*68     + k8 + 4 + c];
      a[3] = Et[(row+8)*68 + k8 + 4 + c];
      #pragma unroll
      for (int ni = 0; ni < 4; ni++){
        int col = ni*8 + r;
        bf[ni][0] = Vs[(k8 + c    )*40 + col];
        bf[ni][1] = Vs[(k8 + 4 + c)*40 + col];
      }
      #pragma unroll
      for (int ni = 0; ni < 4; ni++)
        mma_tf32(av[ni], a, bf[ni]);
    }
  }
  #pragma unroll
  for (int ni = 0; ni < 4; ni++)
    #pragma unroll
    for (int hf = 0; hf < 2; hf++){
      int t = t0 + warp*16 + r + hf*8;
      int cc = h*32 + ni*8 + 2*c;
      size_t base = (size_t)(b*Tq + t)*Eq + cc;
      float2 rv = *(const float2*)&g_xn[base];
      float2 o;
      o.x = av[ni][hf*2  ] + rv.x;
      o.y = av[ni][hf*2+1] + rv.y;
      *(float2*)&g_xh[base] = o;
    }
}

// ---------------- host ----------------
static float* symaddr(const void* sym){
  void* p = nullptr;
  cudaGetSymbolAddress(&p, sym);
  return (float*)p;
}

extern "C" void kernel_launch(void* const* d_in, const int* in_sizes, int n_in,
                              void* d_out, int out_size){
  (void)in_sizes; (void)n_in; (void)out_size;
  const float* x     = (const float*)d_in[0];
  const float* wq    = (const float*)d_in[1];
  const float* wk    = (const float*)d_in[2];
  const float* wv    = (const float*)d_in[3];
  const float* w_lin = (const float*)d_in[4];
  const float* b_lin = (const float*)d_in[5];
  const float* g1    = (const float*)d_in[6];
  const float* beta1 = (const float*)d_in[7];
  const float* g2    = (const float*)d_in[8];
  const float* beta2 = (const float*)d_in[9];
  const float* w_f1  = (const float*)d_in[10];
  const float* b_f1  = (const float*)d_in[11];
  const float* w_f2  = (const float*)d_in[12];
  const float* b_f2  = (const float*)d_in[13];
  float* out = (float*)d_out;

  float* xn  = symaddr(g_xn);
  float* qkv = symaddr(g_qkv);
  float* xh  = symaddr(g_xh);
  float* xl  = symaddr(g_xl);
  float* x2  = symaddr(g_x2);
  float* h1  = symaddr(g_h1);
  float* wp  = symaddr(g_wpack);

  cudaFuncSetAttribute(k_av, cudaFuncAttributeMaxDynamicSharedMemorySize, AV_SMEM);

  k_pack<<<256, 256>>>(wq, wk, wv);
  k_ln<<<BT, 256>>>(x, g1, beta1, xn);
  k_mm<<<dim3(768/64, BT/128), 256>>>(xn, wp, nullptr, nullptr, qkv, 768, Eq, 0);
  k_colsum<<<dim3(32, 64), 256>>>();
  k_av<<<dim3(16, 64), 256, AV_SMEM>>>();
  k_mm<<<dim3(Eq/64, BT/128), 256>>>(xh, w_lin, b_lin, nullptr, xl, Eq, Eq, 0);
  k_ln<<<BT, 256>>>(xl, g2, beta2, x2);
  k_mm<<<dim3(1024/64, BT/128), 256>>>(x2, w_f1, b_f1, nullptr, h1, 1024, Eq, 1);
  k_mm<<<dim3(Eq/64, BT/128), 256>>>(h1, w_f2, b_f2, x2, out, Eq, 1024, 0);
}

// round 4
// speedup vs baseline: 6.5258x; 1.5223x over previous
#include <cuda_runtime.h>
#include <cuda_fp16.h>

#define Tq 2048
#define Eq 256
#define BT 16384        /* 8*2048 */
#define BHq 64
#define SCALE 0.0625f   /* E^-0.5, folded into wq at pack time */

// ---------------- scratch ----------------
__device__ float  g_xn[BT*Eq];
__device__ __half g_qkvh[BT*768];   // half: 0..255 q(prescaled), 256..511 k, 512..767 v; col=h*32+d
__device__ float  g_linv[BHq*Tq];
__device__ float  g_xh[BT*Eq];
__device__ float  g_xl[BT*Eq];
__device__ float  g_x2[BT*Eq];
__device__ __half g_h1h[(size_t)BT*1024];
__device__ __half g_wqkvT[768*256]; // [n][k] half
__device__ __half g_wlinT[256*256];
__device__ __half g_wf1T[1024*256];
__device__ __half g_wf2T[256*1024];

// ---------------- helpers ----------------
__device__ __forceinline__ void mma_f16(float* c, const unsigned* a, const unsigned* b){
  asm volatile("mma.sync.aligned.m16n8k16.row.col.f32.f16.f16.f32 "
               "{%0,%1,%2,%3}, {%4,%5,%6,%7}, {%8,%9}, {%0,%1,%2,%3};\n"
               : "+f"(c[0]), "+f"(c[1]), "+f"(c[2]), "+f"(c[3])
               : "r"(a[0]), "r"(a[1]), "r"(a[2]), "r"(a[3]), "r"(b[0]), "r"(b[1]));
}
__device__ __forceinline__ unsigned ldh2(const __half* p){ return *(const unsigned*)p; }
__device__ __forceinline__ void st4h(__half* dst, float4 v){
  *(__half2*)dst     = __floats2half2_rn(v.x, v.y);
  *(__half2*)(dst+2) = __floats2half2_rn(v.z, v.w);
}
__device__ __forceinline__ void stC(float* C, size_t idx, float v0, float v1){
  float2 o; o.x = v0; o.y = v1; *(float2*)&C[idx] = o;
}
__device__ __forceinline__ void stC(__half* C, size_t idx, float v0, float v1){
  *(__half2*)&C[idx] = __floats2half2_rn(v0, v1);
}

// ---------------- weight prep ----------------
__global__ void k_packT(const float* __restrict__ wq, const float* __restrict__ wk,
                        const float* __restrict__ wv){
  int idx = blockIdx.x*256 + threadIdx.x;
  if (idx >= Eq*Eq) return;
  int c = idx >> 8, e = idx & 255;
  int h = c >> 5, d = c & 31;
  int src = h*Eq*32 + e*32 + d;
  g_wqkvT[(      c)*256 + e] = __float2half(wq[src] * SCALE);
  g_wqkvT[(256 + c)*256 + e] = __float2half(wk[src]);
  g_wqkvT[(512 + c)*256 + e] = __float2half(wv[src]);
}
__global__ void k_wt(const float* __restrict__ src, __half* __restrict__ dst, int N, int K){
  int idx = blockIdx.x*256 + threadIdx.x;
  if (idx >= N*K) return;
  int n = idx / K, k = idx - n*K;
  dst[idx] = __float2half(src[(size_t)k*N + n]);
}

// ---------------- LayerNorm ----------------
__global__ void k_ln(const float* __restrict__ in, const float* __restrict__ g,
                     const float* __restrict__ b, float* __restrict__ out){
  int row = blockIdx.x, tid = threadIdx.x;
  float x = in[(size_t)row*Eq + tid];
  float s = x, s2 = x*x;
  #pragma unroll
  for (int o = 16; o > 0; o >>= 1){
    s  += __shfl_xor_sync(0xffffffffu, s,  o);
    s2 += __shfl_xor_sync(0xffffffffu, s2, o);
  }
  __shared__ float ws[8], ws2[8];
  __shared__ float smean, sinv;
  if ((tid & 31) == 0){ ws[tid>>5] = s; ws2[tid>>5] = s2; }
  __syncthreads();
  if (tid == 0){
    float t = 0.f, t2 = 0.f;
    #pragma unroll
    for (int i = 0; i < 8; i++){ t += ws[i]; t2 += ws2[i]; }
    float mean = t * (1.0f/Eq);
    float var  = t2 * (1.0f/Eq) - mean*mean;
    smean = mean;
    sinv  = rsqrtf(var + 1e-5f);
  }
  __syncthreads();
  out[(size_t)row*Eq + tid] = (x - smean)*sinv*g[tid] + b[tid];
}

// ---------------- A tile staging (float or half source) ----------------
__device__ __forceinline__ void load_tileA(__half (*As)[72], const float* A, int stride,
                                           int m0, int k0, int tid){
  #pragma unroll
  for (int i = 0; i < 8; i++){
    int row = (tid>>4) + 16*i, col = (tid&15)*4;
    float4 v = *(const float4*)&A[(size_t)(m0+row)*stride + k0 + col];
    st4h(&As[row][col], v);
  }
}
__device__ __forceinline__ void load_tileA(__half (*As)[72], const __half* A, int stride,
                                           int m0, int k0, int tid){
  #pragma unroll
  for (int i = 0; i < 4; i++){
    int row = (tid>>3) + 32*i, col = (tid&7)*8;
    *(uint4*)&As[row][col] = *(const uint4*)&A[(size_t)(m0+row)*stride + k0 + col];
  }
}

// ---------------- fp16 GEMM: C(MxN) = A(MxK) @ B^T(stored [N][K] half) ----------------
// tile 128x64, kstep 64, 8 warps (4x2), warp tile 32x32
template<typename TA, typename TC>
__global__ __launch_bounds__(256) void k_mm(
    const TA* __restrict__ A, const __half* __restrict__ Bt,
    const float* __restrict__ bias, const float* __restrict__ res,
    TC* __restrict__ C, int N, int K, int relu)
{
  __shared__ __half As[128][72];
  __shared__ __half Bs[64][72];
  int tid = threadIdx.x, lane = tid & 31, warp = tid >> 5;
  int r = lane >> 2, c = lane & 3;
  int wm = warp >> 1, wn = warp & 1;
  int m0 = blockIdx.y*128, n0 = blockIdx.x*64;
  float acc[2][4][4] = {};

  for (int k0 = 0; k0 < K; k0 += 64){
    load_tileA(As, A, K, m0, k0, tid);
    {
      int nr = tid >> 2, kc = (tid & 3)*16;
      *(uint4*)&Bs[nr][kc  ] = *(const uint4*)&Bt[(size_t)(n0+nr)*K + k0 + kc];
      *(uint4*)&Bs[nr][kc+8] = *(const uint4*)&Bt[(size_t)(n0+nr)*K + k0 + kc + 8];
    }
    __syncthreads();
    #pragma unroll
    for (int ks = 0; ks < 4; ks++){
      int kb = 16*ks + 2*c;
      unsigned a[2][4], b[4][2];
      #pragma unroll
      for (int mi = 0; mi < 2; mi++){
        int row = wm*32 + mi*16 + r;
        a[mi][0] = ldh2(&As[row  ][kb  ]);
        a[mi][1] = ldh2(&As[row+8][kb  ]);
        a[mi][2] = ldh2(&As[row  ][kb+8]);
        a[mi][3] = ldh2(&As[row+8][kb+8]);
      }
      #pragma unroll
      for (int ni = 0; ni < 4; ni++){
        int col = wn*32 + ni*8 + r;
        b[ni][0] = ldh2(&Bs[col][kb  ]);
        b[ni][1] = ldh2(&Bs[col][kb+8]);
      }
      #pragma unroll
      for (int mi = 0; mi < 2; mi++)
        #pragma unroll
        for (int ni = 0; ni < 4; ni++)
          mma_f16(acc[mi][ni], a[mi], b[ni]);
    }
    __syncthreads();
  }
  #pragma unroll
  for (int mi = 0; mi < 2; mi++)
    #pragma unroll
    for (int ni = 0; ni < 4; ni++)
      #pragma unroll
      for (int hf = 0; hf < 2; hf++){
        int rr = m0 + wm*32 + mi*16 + r + hf*8;
        int cc = n0 + wn*32 + ni*8 + 2*c;
        float v0 = acc[mi][ni][hf*2  ];
        float v1 = acc[mi][ni][hf*2+1];
        if (bias){ v0 += bias[cc]; v1 += bias[cc+1]; }
        if (relu){ v0 = fmaxf(v0, 0.f); v1 = fmaxf(v1, 0.f); }
        if (res){
          float2 rv = *(const float2*)&res[(size_t)rr*N + cc];
          v0 += rv.x; v1 += rv.y;
        }
        stC(C, (size_t)rr*N + cc, v0, v1);
      }
}

// ---------------- pass 1: per-column sums of exp(scores), t >= s ----------------
__global__ __launch_bounds__(256) void k_colsum(){
  int s0 = blockIdx.x * 64;
  int z = blockIdx.y;
  int b = z >> 3, h = z & 7;
  int tid = threadIdx.x, lane = tid & 31, warp = tid >> 5;
  int r = lane >> 2, c = lane & 3;
  int wm = warp >> 1, wn = warp & 1;
  __shared__ __half Ks[64][40];
  __shared__ __half Qs[128][40];
  __shared__ float red[8][32];
  const __half* qb = g_qkvh + (size_t)(b*Tq)*768 + h*32;
  const __half* kb = qb + 256;
  {
    int row = tid >> 2, col = (tid & 3)*8;
    *(uint4*)&Ks[row][col] = *(const uint4*)&kb[(size_t)(s0+row)*768 + col];
  }
  float lsum[8] = {};
  int t00 = s0 & ~127;
  for (int t0 = t00; t0 < Tq; t0 += 128){
    __syncthreads();
    #pragma unroll
    for (int i = 0; i < 2; i++){
      int row = (tid>>2) + 64*i, col = (tid & 3)*8;
      *(uint4*)&Qs[row][col] = *(const uint4*)&qb[(size_t)(t0+row)*768 + col];
    }
    __syncthreads();
    float sc[2][4][4] = {};
    #pragma unroll
    for (int ks = 0; ks < 2; ks++){
      int kb2 = 16*ks + 2*c;
      unsigned a[2][4], bf[4][2];
      #pragma unroll
      for (int mi = 0; mi < 2; mi++){
        int row = wm*32 + mi*16 + r;
        a[mi][0] = ldh2(&Qs[row  ][kb2  ]);
        a[mi][1] = ldh2(&Qs[row+8][kb2  ]);
        a[mi][2] = ldh2(&Qs[row  ][kb2+8]);
        a[mi][3] = ldh2(&Qs[row+8][kb2+8]);
      }
      #pragma unroll
      for (int ni = 0; ni < 4; ni++){
        int col = wn*32 + ni*8 + r;
        bf[ni][0] = ldh2(&Ks[col][kb2  ]);
        bf[ni][1] = ldh2(&Ks[col][kb2+8]);
      }
      #pragma unroll
      for (int mi = 0; mi < 2; mi++)
        #pragma unroll
        for (int ni = 0; ni < 4; ni++)
          mma_f16(sc[mi][ni], a[mi], bf[ni]);
    }
    bool dg = (t0 < s0 + 64);
    #pragma unroll
    for (int mi = 0; mi < 2; mi++)
      #pragma unroll
      for (int ni = 0; ni < 4; ni++)
        #pragma unroll
        for (int hf = 0; hf < 2; hf++){
          int rr = wm*32 + mi*16 + r + hf*8;
          int cc = wn*32 + ni*8 + 2*c;
          float e0 = __expf(sc[mi][ni][hf*2  ]);
          float e1 = __expf(sc[mi][ni][hf*2+1]);
          if (dg){
            int tg = t0 + rr;
            if (tg < s0 + cc    ) e0 = 0.f;
            if (tg < s0 + cc + 1) e1 = 0.f;
          }
          lsum[ni*2  ] += e0;
          lsum[ni*2+1] += e1;
        }
  }
  #pragma unroll
  for (int j = 0; j < 8; j++){
    float v = lsum[j];
    v += __shfl_xor_sync(0xffffffffu, v, 4);
    v += __shfl_xor_sync(0xffffffffu, v, 8);
    v += __shfl_xor_sync(0xffffffffu, v, 16);
    lsum[j] = v;
  }
  if (r == 0){
    #pragma unroll
    for (int ni = 0; ni < 4; ni++){
      red[warp][ni*8 + 2*c    ] = lsum[ni*2  ];
      red[warp][ni*8 + 2*c + 1] = lsum[ni*2+1];
    }
  }
  __syncthreads();
  if (tid < 64){
    int wn2 = tid >> 5, lc = tid & 31;
    float tot = red[wn2][lc] + red[2+wn2][lc] + red[4+wn2][lc] + red[6+wn2][lc];
    g_linv[z*Tq + s0 + tid] = 1.0f / tot;
  }
}

// ---------------- pass 2: fused flash AV (fp16), + xn residual ----------------
__global__ __launch_bounds__(256) void k_av(){
  __shared__ __half Qs[128][40];
  __shared__ __half Ks[64][40];
  __shared__ __half Vt[32][74];     // transposed: Vt[d][s]
  __shared__ __half Et[128][72];    // probabilities
  int tt = 15 - blockIdx.x;
  int z = blockIdx.y;
  int b = z >> 3, h = z & 7;
  int t0 = tt*128;
  int tid = threadIdx.x, lane = tid & 31, warp = tid >> 5;
  int r = lane >> 2, c = lane & 3;
  int wm = warp >> 1, wn = warp & 1;
  const __half* qb = g_qkvh + (size_t)(b*Tq)*768 + h*32;
  const __half* kb = qb + 256;
  const __half* vb = qb + 512;
  const float* linv = g_linv + z*Tq;

  #pragma unroll
  for (int i = 0; i < 2; i++){
    int row = (tid>>2) + 64*i, col = (tid & 3)*8;
    *(uint4*)&Qs[row][col] = *(const uint4*)&qb[(size_t)(t0+row)*768 + col];
  }
  float av[4][4] = {};
  for (int s0 = 0; s0 <= t0 + 64; s0 += 64){
    __syncthreads();
    {
      int row = tid >> 2, col = (tid & 3)*8;
      *(uint4*)&Ks[row][col] = *(const uint4*)&kb[(size_t)(s0+row)*768 + col];
      uint4 u = *(const uint4*)&vb[(size_t)(s0+row)*768 + col];
      __half tmp[8]; *(uint4*)tmp = u;
      #pragma unroll
      for (int j = 0; j < 8; j++) Vt[col+j][row] = tmp[j];
    }
    __syncthreads();
    float sc[2][4][4] = {};
    #pragma unroll
    for (int ks = 0; ks < 2; ks++){
      int kb2 = 16*ks + 2*c;
      unsigned a[2][4], bf[4][2];
      #pragma unroll
      for (int mi = 0; mi < 2; mi++){
        int row = wm*32 + mi*16 + r;
        a[mi][0] = ldh2(&Qs[row  ][kb2  ]);
        a[mi][1] = ldh2(&Qs[row+8][kb2  ]);
        a[mi][2] = ldh2(&Qs[row  ][kb2+8]);
        a[mi][3] = ldh2(&Qs[row+8][kb2+8]);
      }
      #pragma unroll
      for (int ni = 0; ni < 4; ni++){
        int col = wn*32 + ni*8 + r;
        bf[ni][0] = ldh2(&Ks[col][kb2  ]);
        bf[ni][1] = ldh2(&Ks[col][kb2+8]);
      }
      #pragma unroll
      for (int mi = 0; mi < 2; mi++)
        #pragma unroll
        for (int ni = 0; ni < 4; ni++)
          mma_f16(sc[mi][ni], a[mi], bf[ni]);
    }
    bool dg = (s0 + 63 > t0);
    float li[4][2];
    #pragma unroll
    for (int ni = 0; ni < 4; ni++){
      li[ni][0] = linv[s0 + wn*32 + ni*8 + 2*c    ];
      li[ni][1] = linv[s0 + wn*32 + ni*8 + 2*c + 1];
    }
    #pragma unroll
    for (int mi = 0; mi < 2; mi++)
      #pragma unroll
      for (int ni = 0; ni < 4; ni++)
        #pragma unroll
        for (int hf = 0; hf < 2; hf++){
          int rr = wm*32 + mi*16 + r + hf*8;
          int cc = wn*32 + ni*8 + 2*c;
          float e0 = __expf(sc[mi][ni][hf*2  ]) * li[ni][0];
          float e1 = __expf(sc[mi][ni][hf*2+1]) * li[ni][1];
          if (dg){
            int tg = t0 + rr;
            if (tg < s0 + cc    ) e0 = 0.f;
            if (tg < s0 + cc + 1) e1 = 0.f;
          }
          *(__half2*)&Et[rr][cc] = __floats2half2_rn(e0, e1);
        }
    __syncthreads();
    #pragma unroll
    for (int ks = 0; ks < 4; ks++){
      int kb2 = 16*ks + 2*c;
      unsigned a[4], bf[4][2];
      int row = warp*16 + r;
      a[0] = ldh2(&Et[row  ][kb2  ]);
      a[1] = ldh2(&Et[row+8][kb2  ]);
      a[2] = ldh2(&Et[row  ][kb2+8]);
      a[3] = ldh2(&Et[row+8][kb2+8]);
      #pragma unroll
      for (int ni = 0; ni < 4; ni++){
        int col = ni*8 + r;
        bf[ni][0] = ldh2(&Vt[col][kb2  ]);
        bf[ni][1] = ldh2(&Vt[col][kb2+8]);
      }
      #pragma unroll
      for (int ni = 0; ni < 4; ni++)
        mma_f16(av[ni], a, bf[ni]);
    }
  }
  #pragma unroll
  for (int ni = 0; ni < 4; ni++)
    #pragma unroll
    for (int hf = 0; hf < 2; hf++){
      int t = t0 + warp*16 + r + hf*8;
      int cc = h*32 + ni*8 + 2*c;
      size_t base = (size_t)(b*Tq + t)*Eq + cc;
      float2 rv = *(const float2*)&g_xn[base];
      float2 o;
      o.x = av[ni][hf*2  ] + rv.x;
      o.y = av[ni][hf*2+1] + rv.y;
      *(float2*)&g_xh[base] = o;
    }
}

// ---------------- host ----------------
static void* symaddr(const void* sym){
  void* p = nullptr;
  cudaGetSymbolAddress(&p, sym);
  return p;
}

extern "C" void kernel_launch(void* const* d_in, const int* in_sizes, int n_in,
                              void* d_out, int out_size){
  (void)in_sizes; (void)n_in; (void)out_size;
  const float* x     = (const float*)d_in[0];
  const float* wq    = (const float*)d_in[1];
  const float* wk    = (const float*)d_in[2];
  const float* wv    = (const float*)d_in[3];
  const float* w_lin = (const float*)d_in[4];
  const float* b_lin = (const float*)d_in[5];
  const float* g1    = (const float*)d_in[6];
  const float* beta1 = (const float*)d_in[7];
  const float* g2    = (const float*)d_in[8];
  const float* beta2 = (const float*)d_in[9];
  const float* w_f1  = (const float*)d_in[10];
  const float* b_f1  = (const float*)d_in[11];
  const float* w_f2  = (const float*)d_in[12];
  const float* b_f2  = (const float*)d_in[13];
  float* out = (float*)d_out;

  float*  xn    = (float*)symaddr(g_xn);
  __half* qkvh  = (__half*)symaddr(g_qkvh);
  float*  xh    = (float*)symaddr(g_xh);
  float*  xl    = (float*)symaddr(g_xl);
  float*  x2    = (float*)symaddr(g_x2);
  __half* h1h   = (__half*)symaddr(g_h1h);
  __half* wqkvT = (__half*)symaddr(g_wqkvT);
  __half* wlinT = (__half*)symaddr(g_wlinT);
  __half* wf1T  = (__half*)symaddr(g_wf1T);
  __half* wf2T  = (__half*)symaddr(g_wf2T);

  k_packT<<<256, 256>>>(wq, wk, wv);
  k_wt<<<256, 256>>>(w_lin, wlinT, 256, 256);
  k_wt<<<1024, 256>>>(w_f1, wf1T, 1024, 256);
  k_wt<<<1024, 256>>>(w_f2, wf2T, 256, 1024);
  k_ln<<<BT, 256>>>(x, g1, beta1, xn);
  k_mm<float,__half><<<dim3(12, 128), 256>>>(xn, wqkvT, nullptr, nullptr, qkvh, 768, 256, 0);
  k_colsum<<<dim3(32, 64), 256>>>();
  k_av<<<dim3(16, 64), 256>>>();
  k_mm<float,float><<<dim3(4, 128), 256>>>(xh, wlinT, b_lin, nullptr, xl, 256, 256, 0);
  k_ln<<<BT, 256>>>(xl, g2, beta2, x2);
  k_mm<float,__half><<<dim3(16, 128), 256>>>(x2, wf1T, b_f1, nullptr, h1h, 1024, 256, 1);
  k_mm<__half,float><<<dim3(4, 128), 256>>>(h1h, wf2T, b_f2, x2, out, 256, 1024, 0);
}